// round 13
// baseline (speedup 1.0000x reference)
#include <cuda_runtime.h>
#include <cstdint>

#define N_DIS 25000
#define N_MIR 25000
#define NTOT  50000
#define EMB   128
#define EDGES 600000

#define SCAN_B 256
#define NBLK ((NTOT + SCAN_B - 1) / SCAN_B)   // 196

// Scratch (device globals: no allocation allowed)
__device__ float g_h   [NTOT * EMB];
__device__ float g_h1  [NTOT * EMB];
__device__ float g_agg1[NTOT * EMB];
__device__ float g_agg2[NTOT * EMB];
__device__ int   g_degi[NTOT];
__device__ float g_inv [NTOT];
__device__ int   g_rowptr[NTOT + 1];
__device__ int   g_cursor[NTOT];
__device__ int   g_esrc[EDGES];
__device__ int   g_bsum[NBLK];
__device__ int   g_boff[NBLK];

// ---------------------------------------------------------------------------
// CSR build
// ---------------------------------------------------------------------------
__global__ void zero_deg_kernel() {
    int i = blockIdx.x * blockDim.x + threadIdx.x;
    if (i < NTOT) g_degi[i] = 0;
}

__global__ void degree_kernel(const int* __restrict__ dst) {
    int e = blockIdx.x * blockDim.x + threadIdx.x;
    if (e < EDGES) atomicAdd(&g_degi[dst[e]], 1);
}

__global__ void scan_p1() {
    __shared__ int ws[8];
    int i = blockIdx.x * SCAN_B + threadIdx.x;
    int v = (i < NTOT) ? g_degi[i] : 0;
    int x = v;
#pragma unroll
    for (int o = 16; o > 0; o >>= 1) x += __shfl_down_sync(0xffffffffu, x, o);
    if ((threadIdx.x & 31) == 0) ws[threadIdx.x >> 5] = x;
    __syncthreads();
    if (threadIdx.x == 0) {
        int s = 0;
#pragma unroll
        for (int w = 0; w < 8; ++w) s += ws[w];
        g_bsum[blockIdx.x] = s;
    }
}

__global__ void scan_p2() {
    __shared__ int sh[256];
    int t = threadIdx.x;
    int v = (t < NBLK) ? g_bsum[t] : 0;
    sh[t] = v;
    __syncthreads();
    for (int o = 1; o < 256; o <<= 1) {
        int y = (t >= o) ? sh[t - o] : 0;
        __syncthreads();
        sh[t] += y;
        __syncthreads();
    }
    if (t < NBLK) g_boff[t] = sh[t] - v;
    if (t == NBLK - 1) g_rowptr[NTOT] = sh[t];
}

__global__ void scan_p3() {
    __shared__ int wsum[8];
    int t = threadIdx.x;
    int i = blockIdx.x * SCAN_B + t;
    int v = (i < NTOT) ? g_degi[i] : 0;
    int x = v;
#pragma unroll
    for (int o = 1; o < 32; o <<= 1) {
        int y = __shfl_up_sync(0xffffffffu, x, o);
        if ((t & 31) >= o) x += y;
    }
    if ((t & 31) == 31) wsum[t >> 5] = x;
    __syncthreads();
    if (t < 8) {
        int s = wsum[t];
#pragma unroll
        for (int o = 1; o < 8; o <<= 1) {
            int y = __shfl_up_sync(0xffu, s, o);
            if (t >= o) s += y;
        }
        wsum[t] = s;
    }
    __syncthreads();
    int warpoff = (t >= 32) ? wsum[(t >> 5) - 1] : 0;
    int excl = g_boff[blockIdx.x] + warpoff + x - v;
    if (i < NTOT) {
        g_rowptr[i] = excl;
        g_cursor[i] = excl;
        g_inv[i] = 1.0f / fmaxf((float)v, 1.0f);
    }
}

__global__ void scatter_kernel(const int* __restrict__ src,
                               const int* __restrict__ dst) {
    int e = blockIdx.x * blockDim.x + threadIdx.x;
    if (e < EDGES) {
        int d = dst[e];
        int pos = atomicAdd(&g_cursor[d], 1);
        g_esrc[pos] = src[e];
    }
}

// ---------------------------------------------------------------------------
// CSR mean-aggregation: one warp per dst node, 8-deep LDG pipeline.
// ---------------------------------------------------------------------------
__global__ __launch_bounds__(256)
void aggregate_csr_kernel(const float* __restrict__ X,
                          float* __restrict__ AGG) {
    int warp = (blockIdx.x * blockDim.x + threadIdx.x) >> 5;
    int lane = threadIdx.x & 31;
    if (warp >= NTOT) return;

    int beg = g_rowptr[warp];
    int end = g_rowptr[warp + 1];
    float inv = g_inv[warp];

    float4 acc = make_float4(0.f, 0.f, 0.f, 0.f);

    int e = beg;
    for (; e + 8 <= end; e += 8) {
        int s0 = g_esrc[e + 0];
        int s1 = g_esrc[e + 1];
        int s2 = g_esrc[e + 2];
        int s3 = g_esrc[e + 3];
        int s4 = g_esrc[e + 4];
        int s5 = g_esrc[e + 5];
        int s6 = g_esrc[e + 6];
        int s7 = g_esrc[e + 7];
        float4 v0 = ((const float4*)(X + (size_t)s0 * EMB))[lane];
        float4 v1 = ((const float4*)(X + (size_t)s1 * EMB))[lane];
        float4 v2 = ((const float4*)(X + (size_t)s2 * EMB))[lane];
        float4 v3 = ((const float4*)(X + (size_t)s3 * EMB))[lane];
        float4 v4 = ((const float4*)(X + (size_t)s4 * EMB))[lane];
        float4 v5 = ((const float4*)(X + (size_t)s5 * EMB))[lane];
        float4 v6 = ((const float4*)(X + (size_t)s6 * EMB))[lane];
        float4 v7 = ((const float4*)(X + (size_t)s7 * EMB))[lane];
        acc.x += ((v0.x + v1.x) + (v2.x + v3.x)) + ((v4.x + v5.x) + (v6.x + v7.x));
        acc.y += ((v0.y + v1.y) + (v2.y + v3.y)) + ((v4.y + v5.y) + (v6.y + v7.y));
        acc.z += ((v0.z + v1.z) + (v2.z + v3.z)) + ((v4.z + v5.z) + (v6.z + v7.z));
        acc.w += ((v0.w + v1.w) + (v2.w + v3.w)) + ((v4.w + v5.w) + (v6.w + v7.w));
    }
    for (; e + 4 <= end; e += 4) {
        int s0 = g_esrc[e + 0];
        int s1 = g_esrc[e + 1];
        int s2 = g_esrc[e + 2];
        int s3 = g_esrc[e + 3];
        float4 v0 = ((const float4*)(X + (size_t)s0 * EMB))[lane];
        float4 v1 = ((const float4*)(X + (size_t)s1 * EMB))[lane];
        float4 v2 = ((const float4*)(X + (size_t)s2 * EMB))[lane];
        float4 v3 = ((const float4*)(X + (size_t)s3 * EMB))[lane];
        acc.x += (v0.x + v1.x) + (v2.x + v3.x);
        acc.y += (v0.y + v1.y) + (v2.y + v3.y);
        acc.z += (v0.z + v1.z) + (v2.z + v3.z);
        acc.w += (v0.w + v1.w) + (v2.w + v3.w);
    }
    for (; e < end; ++e) {
        int s = g_esrc[e];
        float4 v = ((const float4*)(X + (size_t)s * EMB))[lane];
        acc.x += v.x; acc.y += v.y; acc.z += v.z; acc.w += v.w;
    }

    acc.x *= inv; acc.y *= inv; acc.z *= inv; acc.w *= inv;
    ((float4*)(AGG + (size_t)warp * EMB))[lane] = acc;
}

// ---------------------------------------------------------------------------
// TF32 tensor-core GEMM, N fixed at 128. BM=64, 128 threads (4 warps, 2M x 2N,
// warp tile 32x64), BK=32, static smem, ~4 CTAs/SM -> short tail waves.
//   C[M,128] = A[M,K] @ W[K,128] (+ A2[M,128] @ W2) + b   [optional relu]
// ---------------------------------------------------------------------------
#define BM 64
#define BK 32
#define NTHR 128
#define AS_LD 36     // (4r + c) % 32 unique over lanes -> conflict-free A frags
#define BS_LD 136    // (8k + n) % 32 unique over lanes -> conflict-free B frags

__device__ __forceinline__ uint32_t f2tf32(float f) {
    uint32_t u;
    asm("cvt.rna.tf32.f32 %0, %1;" : "=r"(u) : "f"(f));
    return u;
}

__device__ __forceinline__ void mma_tf32(float* d, const uint32_t* a,
                                         const uint32_t* b) {
    asm volatile(
        "mma.sync.aligned.m16n8k8.row.col.f32.tf32.tf32.f32 "
        "{%0,%1,%2,%3}, {%4,%5,%6,%7}, {%8,%9}, {%0,%1,%2,%3};\n"
        : "+f"(d[0]), "+f"(d[1]), "+f"(d[2]), "+f"(d[3])
        : "r"(a[0]), "r"(a[1]), "r"(a[2]), "r"(a[3]), "r"(b[0]), "r"(b[1]));
}

__global__ __launch_bounds__(NTHR)
void gemm128_tc(const float* __restrict__ A, int M, int K,
                const float* __restrict__ W,
                const float* __restrict__ bias,
                const float* __restrict__ A2,   // optional, K2 = 128
                const float* __restrict__ W2,
                float* __restrict__ C,
                int relu) {
    __shared__ uint32_t As[BM][AS_LD];
    __shared__ uint32_t Bs[BK][BS_LD];

    const int tid  = threadIdx.x;
    const int lane = tid & 31;
    const int wid  = tid >> 5;     // 0..3
    const int wm   = wid & 1;      // 0..1 (32-row slab)
    const int wn   = wid >> 1;     // 0..1 (64-col slab)
    const int gid  = lane >> 2;    // 0..7
    const int tig  = lane & 3;     // 0..3
    const int row0 = blockIdx.x * BM;

    float acc[2][8][4];
#pragma unroll
    for (int i = 0; i < 2; ++i)
#pragma unroll
        for (int j = 0; j < 8; ++j)
#pragma unroll
            for (int c = 0; c < 4; ++c) acc[i][j][c] = 0.0f;

    for (int pass = 0; pass < 2; ++pass) {
        const float* Ap;
        const float* Wp;
        int Kp;
        if (pass == 0) {
            Ap = A; Wp = W; Kp = K;
        } else {
            if (A2 == nullptr) break;
            Ap = A2; Wp = W2; Kp = EMB;
        }
        const bool vecA = ((Kp & 3) == 0);

        for (int k0 = 0; k0 < Kp; k0 += BK) {
            // --- A tile: 64 rows x 32 k ---
            if (vecA) {
#pragma unroll
                for (int it = 0; it < (BM * BK / 4) / NTHR; ++it) {   // 4 iters
                    int idx = tid + it * NTHR;
                    int r  = idx >> 3;          // 0..63
                    int cg = idx & 7;
                    int gr = row0 + r;
                    int gk = k0 + cg * 4;
                    uint4 o;
                    if (gr < M && gk + 3 < Kp) {
                        float4 v = *(const float4*)(Ap + (size_t)gr * Kp + gk);
                        o.x = f2tf32(v.x); o.y = f2tf32(v.y);
                        o.z = f2tf32(v.z); o.w = f2tf32(v.w);
                    } else {
                        o = make_uint4(0u, 0u, 0u, 0u);
                    }
                    *(uint4*)&As[r][cg * 4] = o;
                }
            } else {
#pragma unroll
                for (int it = 0; it < (BM * BK) / NTHR; ++it) {       // 16 iters
                    int idx = tid + it * NTHR;
                    int r = idx >> 5;           // 0..63
                    int c = idx & 31;
                    int gr = row0 + r;
                    int gk = k0 + c;
                    uint32_t u = 0u;
                    if (gr < M && gk < Kp) u = f2tf32(Ap[(size_t)gr * Kp + gk]);
                    As[r][c] = u;
                }
            }
            // --- B tile: 32 k x 128 n ---
#pragma unroll
            for (int it = 0; it < (BK * EMB / 4) / NTHR; ++it) {      // 8 iters
                int idx = tid + it * NTHR;
                int kk = idx >> 5;              // 0..31
                int cg = idx & 31;
                int gk = k0 + kk;
                uint4 o;
                if (gk < Kp) {
                    float4 v = *(const float4*)(Wp + (size_t)gk * EMB + cg * 4);
                    o.x = f2tf32(v.x); o.y = f2tf32(v.y);
                    o.z = f2tf32(v.z); o.w = f2tf32(v.w);
                } else {
                    o = make_uint4(0u, 0u, 0u, 0u);
                }
                *(uint4*)&Bs[kk][cg * 4] = o;
            }
            __syncthreads();

#pragma unroll
            for (int ks = 0; ks < 4; ++ks) {
                const int kb = ks * 8;
                uint32_t af[2][4];
                uint32_t bf[8][2];
#pragma unroll
                for (int i = 0; i < 2; ++i) {
                    int r = wm * 32 + i * 16 + gid;
                    af[i][0] = As[r][kb + tig];
                    af[i][1] = As[r + 8][kb + tig];
                    af[i][2] = As[r][kb + tig + 4];
                    af[i][3] = As[r + 8][kb + tig + 4];
                }
#pragma unroll
                for (int j = 0; j < 8; ++j) {
                    int n = wn * 64 + j * 8 + gid;
                    bf[j][0] = Bs[kb + tig][n];
                    bf[j][1] = Bs[kb + tig + 4][n];
                }
#pragma unroll
                for (int i = 0; i < 2; ++i)
#pragma unroll
                    for (int j = 0; j < 8; ++j)
                        mma_tf32(acc[i][j], af[i], bf[j]);
            }
            __syncthreads();
        }
    }

    // --- epilogue: bias (+relu), float2 stores ---
#pragma unroll
    for (int i = 0; i < 2; ++i) {
        int r0g = row0 + wm * 32 + i * 16 + gid;
#pragma unroll
        for (int j = 0; j < 8; ++j) {
            int col = wn * 64 + j * 8 + 2 * tig;
            float bx = bias[col];
            float by = bias[col + 1];
            float2 o0, o1;
            o0.x = acc[i][j][0] + bx;  o0.y = acc[i][j][1] + by;
            o1.x = acc[i][j][2] + bx;  o1.y = acc[i][j][3] + by;
            if (relu) {
                o0.x = fmaxf(o0.x, 0.f); o0.y = fmaxf(o0.y, 0.f);
                o1.x = fmaxf(o1.x, 0.f); o1.y = fmaxf(o1.y, 0.f);
            }
            if (r0g < M)     *(float2*)&C[(size_t)r0g * EMB + col]       = o0;
            if (r0g + 8 < M) *(float2*)&C[(size_t)(r0g + 8) * EMB + col] = o1;
        }
    }
}

// ---------------------------------------------------------------------------
// Launch: CSR build (side stream) ∥ projection GEMMs (main), then sequential.
// ---------------------------------------------------------------------------
extern "C" void kernel_launch(void* const* d_in, const int* in_sizes, int n_in,
                              void* d_out, int out_size) {
    const float* d_feat = (const float*)d_in[0];
    const float* m_feat = (const float*)d_in[1];
    const int*   src    = (const int*)d_in[2];
    const int*   dst    = (const int*)d_in[3];
    const float* W_d    = (const float*)d_in[4];
    const float* b_d    = (const float*)d_in[5];
    const float* W_m    = (const float*)d_in[6];
    const float* b_m    = (const float*)d_in[7];
    const float* W_s1   = (const float*)d_in[8];
    const float* W_n1   = (const float*)d_in[9];
    const float* b1     = (const float*)d_in[10];
    const float* W_s2   = (const float*)d_in[11];
    const float* W_n2   = (const float*)d_in[12];
    const float* b2     = (const float*)d_in[13];
    float* out = (float*)d_out;

    float *h, *h1, *agg1, *agg2;
    {
        void* p;
        cudaGetSymbolAddress(&p, g_h);    h    = (float*)p;
        cudaGetSymbolAddress(&p, g_h1);   h1   = (float*)p;
        cudaGetSymbolAddress(&p, g_agg1); agg1 = (float*)p;
        cudaGetSymbolAddress(&p, g_agg2); agg2 = (float*)p;
    }

    cudaStream_t s2;
    cudaStreamCreateWithFlags(&s2, cudaStreamNonBlocking);
    cudaEvent_t evFork, evCSR;
    cudaEventCreateWithFlags(&evFork, cudaEventDisableTiming);
    cudaEventCreateWithFlags(&evCSR,  cudaEventDisableTiming);

    // ---- fork ----
    cudaEventRecord(evFork, 0);
    cudaStreamWaitEvent(s2, evFork, 0);

    // CSR build on side stream
    zero_deg_kernel<<<(NTOT + 255) / 256, 256, 0, s2>>>();
    degree_kernel<<<(EDGES + 255) / 256, 256, 0, s2>>>(dst);
    scan_p1<<<NBLK, SCAN_B, 0, s2>>>();
    scan_p2<<<1, 256, 0, s2>>>();
    scan_p3<<<NBLK, SCAN_B, 0, s2>>>();
    scatter_kernel<<<(EDGES + 255) / 256, 256, 0, s2>>>(src, dst);
    cudaEventRecord(evCSR, s2);

    // Projection GEMMs on main stream
    gemm128_tc<<<(N_DIS + BM - 1) / BM, NTHR>>>(d_feat, N_DIS, 383, W_d, b_d,
                                                nullptr, nullptr, h, 0);
    gemm128_tc<<<(N_MIR + BM - 1) / BM, NTHR>>>(m_feat, N_MIR, 495, W_m, b_m,
                                                nullptr, nullptr,
                                                h + (size_t)N_DIS * EMB, 0);

    // ---- join ----
    cudaStreamWaitEvent(0, evCSR, 0);

    // Layer 1
    aggregate_csr_kernel<<<(NTOT * 32 + 255) / 256, 256>>>(h, agg1);
    gemm128_tc<<<(NTOT + BM - 1) / BM, NTHR>>>(h, NTOT, EMB, W_s1, b1,
                                               agg1, W_n1, h1, 1);

    // Layer 2
    aggregate_csr_kernel<<<(NTOT * 32 + 255) / 256, 256>>>(h1, agg2);
    gemm128_tc<<<(NTOT + BM - 1) / BM, NTHR>>>(h1, NTOT, EMB, W_s2, b2,
                                               agg2, W_n2, out, 0);
}

// round 14
// speedup vs baseline: 1.6855x; 1.6855x over previous
#include <cuda_runtime.h>
#include <cstdint>

#define N_DIS 25000
#define N_MIR 25000
#define NTOT  50000
#define EMB   128
#define EDGES 600000
#define K_DIS 383
#define K_MIR 495

#define SCAN_B 256
#define NBLK ((NTOT + SCAN_B - 1) / SCAN_B)   // 196

// Scratch (device globals: no allocation allowed)
__device__ float g_h   [NTOT * EMB];
__device__ float g_h1  [NTOT * EMB];
__device__ float g_agg1[NTOT * EMB];
__device__ float g_agg2[NTOT * EMB];
__device__ int   g_degi[NTOT];
__device__ float g_inv [NTOT];
__device__ int   g_rowptr[NTOT + 1];
__device__ int   g_cursor[NTOT];
__device__ int   g_esrc[EDGES];
__device__ int   g_bsum[NBLK];
__device__ int   g_boff[NBLK];

// ---------------------------------------------------------------------------
// CSR build
// ---------------------------------------------------------------------------
__global__ void zero_deg_kernel() {
    int i = blockIdx.x * blockDim.x + threadIdx.x;
    if (i < NTOT) g_degi[i] = 0;
}

__global__ void degree_kernel(const int* __restrict__ dst) {
    int e = blockIdx.x * blockDim.x + threadIdx.x;
    if (e < EDGES) atomicAdd(&g_degi[dst[e]], 1);
}

__global__ void scan_p1() {
    __shared__ int ws[8];
    int i = blockIdx.x * SCAN_B + threadIdx.x;
    int v = (i < NTOT) ? g_degi[i] : 0;
    int x = v;
#pragma unroll
    for (int o = 16; o > 0; o >>= 1) x += __shfl_down_sync(0xffffffffu, x, o);
    if ((threadIdx.x & 31) == 0) ws[threadIdx.x >> 5] = x;
    __syncthreads();
    if (threadIdx.x == 0) {
        int s = 0;
#pragma unroll
        for (int w = 0; w < 8; ++w) s += ws[w];
        g_bsum[blockIdx.x] = s;
    }
}

__global__ void scan_p2() {
    __shared__ int sh[256];
    int t = threadIdx.x;
    int v = (t < NBLK) ? g_bsum[t] : 0;
    sh[t] = v;
    __syncthreads();
    for (int o = 1; o < 256; o <<= 1) {
        int y = (t >= o) ? sh[t - o] : 0;
        __syncthreads();
        sh[t] += y;
        __syncthreads();
    }
    if (t < NBLK) g_boff[t] = sh[t] - v;
    if (t == NBLK - 1) g_rowptr[NTOT] = sh[t];
}

__global__ void scan_p3() {
    __shared__ int wsum[8];
    int t = threadIdx.x;
    int i = blockIdx.x * SCAN_B + t;
    int v = (i < NTOT) ? g_degi[i] : 0;
    int x = v;
#pragma unroll
    for (int o = 1; o < 32; o <<= 1) {
        int y = __shfl_up_sync(0xffffffffu, x, o);
        if ((t & 31) >= o) x += y;
    }
    if ((t & 31) == 31) wsum[t >> 5] = x;
    __syncthreads();
    if (t < 8) {
        int s = wsum[t];
#pragma unroll
        for (int o = 1; o < 8; o <<= 1) {
            int y = __shfl_up_sync(0xffu, s, o);
            if (t >= o) s += y;
        }
        wsum[t] = s;
    }
    __syncthreads();
    int warpoff = (t >= 32) ? wsum[(t >> 5) - 1] : 0;
    int excl = g_boff[blockIdx.x] + warpoff + x - v;
    if (i < NTOT) {
        g_rowptr[i] = excl;
        g_cursor[i] = excl;
        g_inv[i] = 1.0f / fmaxf((float)v, 1.0f);
    }
}

__global__ void scatter_kernel(const int* __restrict__ src,
                               const int* __restrict__ dst) {
    int e = blockIdx.x * blockDim.x + threadIdx.x;
    if (e < EDGES) {
        int d = dst[e];
        int pos = atomicAdd(&g_cursor[d], 1);
        g_esrc[pos] = src[e];
    }
}

// ---------------------------------------------------------------------------
// CSR mean-aggregation: one warp per dst node, 8-deep LDG pipeline.
// ---------------------------------------------------------------------------
__global__ __launch_bounds__(256)
void aggregate_csr_kernel(const float* __restrict__ X,
                          float* __restrict__ AGG) {
    int warp = (blockIdx.x * blockDim.x + threadIdx.x) >> 5;
    int lane = threadIdx.x & 31;
    if (warp >= NTOT) return;

    int beg = g_rowptr[warp];
    int end = g_rowptr[warp + 1];
    float inv = g_inv[warp];

    float4 acc = make_float4(0.f, 0.f, 0.f, 0.f);

    int e = beg;
    for (; e + 8 <= end; e += 8) {
        int s0 = g_esrc[e + 0];
        int s1 = g_esrc[e + 1];
        int s2 = g_esrc[e + 2];
        int s3 = g_esrc[e + 3];
        int s4 = g_esrc[e + 4];
        int s5 = g_esrc[e + 5];
        int s6 = g_esrc[e + 6];
        int s7 = g_esrc[e + 7];
        float4 v0 = ((const float4*)(X + (size_t)s0 * EMB))[lane];
        float4 v1 = ((const float4*)(X + (size_t)s1 * EMB))[lane];
        float4 v2 = ((const float4*)(X + (size_t)s2 * EMB))[lane];
        float4 v3 = ((const float4*)(X + (size_t)s3 * EMB))[lane];
        float4 v4 = ((const float4*)(X + (size_t)s4 * EMB))[lane];
        float4 v5 = ((const float4*)(X + (size_t)s5 * EMB))[lane];
        float4 v6 = ((const float4*)(X + (size_t)s6 * EMB))[lane];
        float4 v7 = ((const float4*)(X + (size_t)s7 * EMB))[lane];
        acc.x += ((v0.x + v1.x) + (v2.x + v3.x)) + ((v4.x + v5.x) + (v6.x + v7.x));
        acc.y += ((v0.y + v1.y) + (v2.y + v3.y)) + ((v4.y + v5.y) + (v6.y + v7.y));
        acc.z += ((v0.z + v1.z) + (v2.z + v3.z)) + ((v4.z + v5.z) + (v6.z + v7.z));
        acc.w += ((v0.w + v1.w) + (v2.w + v3.w)) + ((v4.w + v5.w) + (v6.w + v7.w));
    }
    for (; e + 4 <= end; e += 4) {
        int s0 = g_esrc[e + 0];
        int s1 = g_esrc[e + 1];
        int s2 = g_esrc[e + 2];
        int s3 = g_esrc[e + 3];
        float4 v0 = ((const float4*)(X + (size_t)s0 * EMB))[lane];
        float4 v1 = ((const float4*)(X + (size_t)s1 * EMB))[lane];
        float4 v2 = ((const float4*)(X + (size_t)s2 * EMB))[lane];
        float4 v3 = ((const float4*)(X + (size_t)s3 * EMB))[lane];
        acc.x += (v0.x + v1.x) + (v2.x + v3.x);
        acc.y += (v0.y + v1.y) + (v2.y + v3.y);
        acc.z += (v0.z + v1.z) + (v2.z + v3.z);
        acc.w += (v0.w + v1.w) + (v2.w + v3.w);
    }
    for (; e < end; ++e) {
        int s = g_esrc[e];
        float4 v = ((const float4*)(X + (size_t)s * EMB))[lane];
        acc.x += v.x; acc.y += v.y; acc.z += v.z; acc.w += v.w;
    }

    acc.x *= inv; acc.y *= inv; acc.z *= inv; acc.w *= inv;
    ((float4*)(AGG + (size_t)warp * EMB))[lane] = acc;
}

// ---------------------------------------------------------------------------
// TF32 tensor-core GEMM body (R9-proven config: 256 thr, 8 warps 2Mx4N,
// block tile 128x128, BK=32, static smem, 2 CTAs/SM). ONE call site per kernel.
// ---------------------------------------------------------------------------
#define BM 128
#define BK 32
#define AS_LD 36
#define BS_LD 136

__device__ __forceinline__ uint32_t f2tf32(float f) {
    uint32_t u;
    asm("cvt.rna.tf32.f32 %0, %1;" : "=r"(u) : "f"(f));
    return u;
}

__device__ __forceinline__ void mma_tf32(float* d, const uint32_t* a,
                                         const uint32_t* b) {
    asm volatile(
        "mma.sync.aligned.m16n8k8.row.col.f32.tf32.tf32.f32 "
        "{%0,%1,%2,%3}, {%4,%5,%6,%7}, {%8,%9}, {%0,%1,%2,%3};\n"
        : "+f"(d[0]), "+f"(d[1]), "+f"(d[2]), "+f"(d[3])
        : "r"(a[0]), "r"(a[1]), "r"(a[2]), "r"(a[3]), "r"(b[0]), "r"(b[1]));
}

__device__ __forceinline__ void gemm_body(
    const float* __restrict__ A, int M, int K,
    const float* __restrict__ W,
    const float* __restrict__ bias,
    const float* __restrict__ A2,   // optional, K2 = 128
    const float* __restrict__ W2,
    float* __restrict__ C,
    int relu, int row0) {

    __shared__ uint32_t As[BM][AS_LD];
    __shared__ uint32_t Bs[BK][BS_LD];

    const int tid  = threadIdx.x;
    const int lane = tid & 31;
    const int wid  = tid >> 5;
    const int wm   = wid & 1;
    const int wn   = wid >> 1;
    const int gid  = lane >> 2;
    const int tig  = lane & 3;

    float acc[4][4][4];
#pragma unroll
    for (int i = 0; i < 4; ++i)
#pragma unroll
        for (int j = 0; j < 4; ++j)
#pragma unroll
            for (int c = 0; c < 4; ++c) acc[i][j][c] = 0.0f;

    for (int pass = 0; pass < 2; ++pass) {
        const float* Ap;
        const float* Wp;
        int Kp;
        if (pass == 0) {
            Ap = A; Wp = W; Kp = K;
        } else {
            if (A2 == nullptr) break;
            Ap = A2; Wp = W2; Kp = EMB;
        }
        const bool vecA = ((Kp & 3) == 0);

        for (int k0 = 0; k0 < Kp; k0 += BK) {
            if (vecA) {
#pragma unroll
                for (int it = 0; it < (BM * BK / 4) / 256; ++it) {
                    int idx = tid + it * 256;
                    int r  = idx >> 3;
                    int cg = idx & 7;
                    int gr = row0 + r;
                    int gk = k0 + cg * 4;
                    uint4 o;
                    if (gr < M && gk + 3 < Kp) {
                        float4 v = *(const float4*)(Ap + (size_t)gr * Kp + gk);
                        o.x = f2tf32(v.x); o.y = f2tf32(v.y);
                        o.z = f2tf32(v.z); o.w = f2tf32(v.w);
                    } else {
                        o = make_uint4(0u, 0u, 0u, 0u);
                    }
                    *(uint4*)&As[r][cg * 4] = o;
                }
            } else {
#pragma unroll
                for (int it = 0; it < (BM * BK) / 256; ++it) {
                    int idx = tid + it * 256;
                    int r = idx >> 5;
                    int c = idx & 31;
                    int gr = row0 + r;
                    int gk = k0 + c;
                    uint32_t u = 0u;
                    if (gr < M && gk < Kp) u = f2tf32(Ap[(size_t)gr * Kp + gk]);
                    As[r][c] = u;
                }
            }
#pragma unroll
            for (int it = 0; it < (BK * EMB / 4) / 256; ++it) {
                int idx = tid + it * 256;
                int kk = idx >> 5;
                int cg = idx & 31;
                int gk = k0 + kk;
                uint4 o;
                if (gk < Kp) {
                    float4 v = *(const float4*)(Wp + (size_t)gk * EMB + cg * 4);
                    o.x = f2tf32(v.x); o.y = f2tf32(v.y);
                    o.z = f2tf32(v.z); o.w = f2tf32(v.w);
                } else {
                    o = make_uint4(0u, 0u, 0u, 0u);
                }
                *(uint4*)&Bs[kk][cg * 4] = o;
            }
            __syncthreads();

#pragma unroll
            for (int ks = 0; ks < 4; ++ks) {
                const int kb = ks * 8;
                uint32_t af[4][4];
                uint32_t bf[4][2];
#pragma unroll
                for (int i = 0; i < 4; ++i) {
                    int r = wm * 64 + i * 16 + gid;
                    af[i][0] = As[r][kb + tig];
                    af[i][1] = As[r + 8][kb + tig];
                    af[i][2] = As[r][kb + tig + 4];
                    af[i][3] = As[r + 8][kb + tig + 4];
                }
#pragma unroll
                for (int j = 0; j < 4; ++j) {
                    int n = wn * 32 + j * 8 + gid;
                    bf[j][0] = Bs[kb + tig][n];
                    bf[j][1] = Bs[kb + tig + 4][n];
                }
#pragma unroll
                for (int i = 0; i < 4; ++i)
#pragma unroll
                    for (int j = 0; j < 4; ++j)
                        mma_tf32(acc[i][j], af[i], bf[j]);
            }
            __syncthreads();
        }
    }

#pragma unroll
    for (int i = 0; i < 4; ++i) {
        int r0g = row0 + wm * 64 + i * 16 + gid;
#pragma unroll
        for (int j = 0; j < 4; ++j) {
            int col = wn * 32 + j * 8 + 2 * tig;
            float bx = bias[col];
            float by = bias[col + 1];
            float2 o0, o1;
            o0.x = acc[i][j][0] + bx;  o0.y = acc[i][j][1] + by;
            o1.x = acc[i][j][2] + bx;  o1.y = acc[i][j][3] + by;
            if (relu) {
                o0.x = fmaxf(o0.x, 0.f); o0.y = fmaxf(o0.y, 0.f);
                o1.x = fmaxf(o1.x, 0.f); o1.y = fmaxf(o1.y, 0.f);
            }
            if (r0g < M)     *(float2*)&C[(size_t)r0g * EMB + col]       = o0;
            if (r0g + 8 < M) *(float2*)&C[(size_t)(r0g + 8) * EMB + col] = o1;
        }
    }
}

// Layer GEMM kernel — single gemm_body call site (identical to R9 codegen).
__global__ __launch_bounds__(256)
void gemm128_tc(const float* __restrict__ A, int M, int K,
                const float* __restrict__ W,
                const float* __restrict__ bias,
                const float* __restrict__ A2,
                const float* __restrict__ W2,
                float* __restrict__ C,
                int relu) {
    gemm_body(A, M, K, W, bias, A2, W2, C, relu, blockIdx.x * BM);
}

// Merged projection kernel — parameters selected BEFORE the single call site,
// so gemm_body is instantiated exactly once (fixes R11's double-inline bloat).
#define NB_DIS ((N_DIS + BM - 1) / BM)   // 196
#define NB_MIR ((N_MIR + BM - 1) / BM)   // 196
__global__ __launch_bounds__(256)
void gemm_proj(const float* __restrict__ d_feat,
               const float* __restrict__ W_d, const float* __restrict__ b_d,
               const float* __restrict__ m_feat,
               const float* __restrict__ W_m, const float* __restrict__ b_m,
               float* __restrict__ h) {
    const float* A;
    const float* W;
    const float* bias;
    float* C;
    int K, row0;
    if (blockIdx.x < NB_DIS) {
        A = d_feat; W = W_d; bias = b_d; C = h;
        K = K_DIS;  row0 = blockIdx.x * BM;
    } else {
        A = m_feat; W = W_m; bias = b_m; C = h + (size_t)N_DIS * EMB;
        K = K_MIR;  row0 = (blockIdx.x - NB_DIS) * BM;
    }
    gemm_body(A, N_DIS /* == N_MIR */, K, W, bias, nullptr, nullptr, C, 0, row0);
}

// ---------------------------------------------------------------------------
// Launch: CSR build (side stream) ∥ merged projection GEMM (main).
// ---------------------------------------------------------------------------
extern "C" void kernel_launch(void* const* d_in, const int* in_sizes, int n_in,
                              void* d_out, int out_size) {
    const float* d_feat = (const float*)d_in[0];
    const float* m_feat = (const float*)d_in[1];
    const int*   src    = (const int*)d_in[2];
    const int*   dst    = (const int*)d_in[3];
    const float* W_d    = (const float*)d_in[4];
    const float* b_d    = (const float*)d_in[5];
    const float* W_m    = (const float*)d_in[6];
    const float* b_m    = (const float*)d_in[7];
    const float* W_s1   = (const float*)d_in[8];
    const float* W_n1   = (const float*)d_in[9];
    const float* b1     = (const float*)d_in[10];
    const float* W_s2   = (const float*)d_in[11];
    const float* W_n2   = (const float*)d_in[12];
    const float* b2     = (const float*)d_in[13];
    float* out = (float*)d_out;

    float *h, *h1, *agg1, *agg2;
    {
        void* p;
        cudaGetSymbolAddress(&p, g_h);    h    = (float*)p;
        cudaGetSymbolAddress(&p, g_h1);   h1   = (float*)p;
        cudaGetSymbolAddress(&p, g_agg1); agg1 = (float*)p;
        cudaGetSymbolAddress(&p, g_agg2); agg2 = (float*)p;
    }

    cudaStream_t s2;
    cudaStreamCreateWithFlags(&s2, cudaStreamNonBlocking);
    cudaEvent_t evFork, evCSR;
    cudaEventCreateWithFlags(&evFork, cudaEventDisableTiming);
    cudaEventCreateWithFlags(&evCSR,  cudaEventDisableTiming);

    // ---- fork ----
    cudaEventRecord(evFork, 0);
    cudaStreamWaitEvent(s2, evFork, 0);

    // CSR build on side stream
    zero_deg_kernel<<<(NTOT + 255) / 256, 256, 0, s2>>>();
    degree_kernel<<<(EDGES + 255) / 256, 256, 0, s2>>>(dst);
    scan_p1<<<NBLK, SCAN_B, 0, s2>>>();
    scan_p2<<<1, 256, 0, s2>>>();
    scan_p3<<<NBLK, SCAN_B, 0, s2>>>();
    scatter_kernel<<<(EDGES + 255) / 256, 256, 0, s2>>>(src, dst);
    cudaEventRecord(evCSR, s2);

    // Merged projection GEMM on main stream (one launch, 392 blocks)
    gemm_proj<<<NB_DIS + NB_MIR, 256>>>(d_feat, W_d, b_d,
                                        m_feat, W_m, b_m, h);

    // ---- join ----
    cudaStreamWaitEvent(0, evCSR, 0);

    // Layer 1
    aggregate_csr_kernel<<<(NTOT * 32 + 255) / 256, 256>>>(h, agg1);
    gemm128_tc<<<(NTOT + BM - 1) / BM, 256>>>(h, NTOT, EMB, W_s1, b1,
                                              agg1, W_n1, h1, 1);

    // Layer 2
    aggregate_csr_kernel<<<(NTOT * 32 + 255) / 256, 256>>>(h1, agg2);
    gemm128_tc<<<(NTOT + BM - 1) / BM, 256>>>(h1, NTOT, EMB, W_s2, b2,
                                              agg2, W_n2, out, 0);
}